// round 12
// baseline (speedup 1.0000x reference)
#include <cuda_runtime.h>

// RawStack fused 10-layer dilated conv stack — high-occupancy register version.
// R4/R6: RR=16 elems/lane (32 data regs), NW=16 warps (512 thr),
//   __launch_bounds__(512,2) -> target 64 regs -> 32 warps/SM (2 CTAs).
// Layers 0-3 (d=1..8): contiguous layout, D-value prefetch via shfl_down(1).
// Layer  4  (d=16=RR): tail is entirely next lane -> JIT shfl in the loop.
// Padded-stride-17 warp-local SMEM transpose to strided layout (e = r*32+l).
// Layers 5-8 (d=32..256): disjoint xchB sub-regions -> 1 barrier/layer.
// Layer  9  (d=512, Q=16=RR): full-buffer publish (overlaps 5-8 regions) ->
//   pre-publish barrier + publish barrier; operands all from next warp (JIT LDS).

#define T_IN     131072
#define HALO     1023
#define T_OUT    (T_IN - HALO)          // 130049
#define NW       16                     // warps per CTA
#define RR       16                     // elements per lane per array
#define WCH      (RR * 32)              // 512 elements per warp
#define CTA_IN   (NW * WCH)             // 8192
#define TILE_OUT ((NW - 2) * WCH)       // 7168 (warps 14,15 = halo)
#define NTILES   ((T_OUT + TILE_OUT - 1) / TILE_OUT)   // 19
#define THREADS  (NW * 32)              // 512
#define BATCH    64

struct Smem {
    float xchA[2][NW][32];   // phase-A head exchange: h at [0,16), x at [16,32)
    float xchB[NW][1024];    // phase-B exchange; layers 5-8 use disjoint
                             // sub-regions (960 fl), layer 9 uses all 1024;
                             // also reused as per-warp transpose buffer (542 fl)
};

// Hardware tanh approximation (MUFU.TANH), single MUFU op.
__device__ __forceinline__ float fast_tanh(float v) {
    float r;
    asm("tanh.approx.f32 %0, %1;" : "=f"(r) : "f"(v));
    return r;
}

// ---- Phase A layer (contiguous layout, elem = l*RR + r): d = 1<<I ----
template<int I>
__device__ __forceinline__ void layerA(float (&h)[RR], float (&x)[RR],
                                       Smem* sm, int w, int l,
                                       const float* __restrict__ wh,
                                       const float* __restrict__ wx)
{
    constexpr int D = 1 << I;      // 1..16
    constexpr int P = I & 1;
    const float wh0 = __ldg(&wh[2*I]), wh1 = __ldg(&wh[2*I+1]);
    const float wx0 = __ldg(&wx[2*I]), wx1 = __ldg(&wx[2*I+1]);

    const int wn = (w < NW - 1) ? (w + 1) : w;     // clamped (no OOB smem)
    const float gate = (w < NW - 1) ? 1.0f : 0.0f; // zero past CTA window

    // publish this warp's lane-0 head [0,D) (pre-update) for warp w-1
    if (l == 0) {
        #pragma unroll
        for (int j = 0; j < D; j++) {
            sm->xchA[P][w][j]      = h[j];
            sm->xchA[P][w][16 + j] = x[j];
        }
    }
    __syncthreads();

    if constexpr (D < RR) {
        // prefetch the D tail-neighbor values (pre-update) before any update
        float nh[D], nx[D];
        #pragma unroll
        for (int j = 0; j < D; j++) {
            float vh = __shfl_down_sync(0xffffffffu, h[j], 1);
            float vx = __shfl_down_sync(0xffffffffu, x[j], 1);
            if (l == 31) {
                vh = gate * sm->xchA[P][wn][j];
                vx = gate * sm->xchA[P][wn][16 + j];
            }
            nh[j] = vh; nx[j] = vx;
        }
        #pragma unroll
        for (int r = 0; r < RR; r++) {
            float hd = (r + D < RR) ? h[r + D] : nh[r + D - RR];
            float xd = (r + D < RR) ? x[r + D] : nx[r + D - RR];
            float hn = fmaf(wh1, hd, wh0 * h[r]);
            float xn = fmaf(wx1, xd, wx0 * x[r]);
            h[r] = hn;
            x[r] = fast_tanh(hn + xn);
        }
    } else {
        // D == RR: every tail value is next lane's h[r]/x[r] -> JIT shfl.
        // Lockstep SIMT + WAR ordering: shfl of h[r] precedes write of h[r],
        // so all lanes read pre-update values.
        #pragma unroll
        for (int r = 0; r < RR; r++) {
            float vh = __shfl_down_sync(0xffffffffu, h[r], 1);
            float vx = __shfl_down_sync(0xffffffffu, x[r], 1);
            if (l == 31) {
                vh = gate * sm->xchA[P][wn][r];
                vx = gate * sm->xchA[P][wn][16 + r];
            }
            float hn = fmaf(wh1, vh, wh0 * h[r]);
            float xn = fmaf(wx1, vx, wx0 * x[r]);
            h[r] = hn;
            x[r] = fast_tanh(hn + xn);
        }
    }
}

// Disjoint xchB sub-region offsets (floats, per warp) for layers 5..8:
//   L5: h@0   x@32    (Q=1 -> 32 each)
//   L6: h@64  x@128   (Q=2 -> 64 each)
//   L7: h@192 x@320   (Q=4 -> 128 each)
//   L8: h@448 x@704   (Q=8 -> 256 each)   ends at 960 <= 1024
//   L9: h@0   x@512   (Q=16 -> 512 each)  full buffer, overlaps 5-8
template<int I> struct BOff;
template<> struct BOff<5> { static constexpr int H = 0,   X = 32;  };
template<> struct BOff<6> { static constexpr int H = 64,  X = 128; };
template<> struct BOff<7> { static constexpr int H = 192, X = 320; };
template<> struct BOff<8> { static constexpr int H = 448, X = 704; };
template<> struct BOff<9> { static constexpr int H = 0,   X = 512; };

// ---- Phase B layer (strided layout, elem = r*32 + l): d = 32<<(I-5) ----
template<int I>
__device__ __forceinline__ void layerB(float (&h)[RR], float (&x)[RR],
                                       Smem* sm, int w, int l,
                                       const float* __restrict__ wh,
                                       const float* __restrict__ wx)
{
    constexpr int Q  = 1 << (I - 5);    // d/32 = 1..16
    constexpr int OH = BOff<I>::H;
    constexpr int OX = BOff<I>::X;
    const float wh0 = __ldg(&wh[2*I]), wh1 = __ldg(&wh[2*I+1]);
    const float wx0 = __ldg(&wx[2*I]), wx1 = __ldg(&wx[2*I+1]);

    const int wn = (w < NW - 1) ? (w + 1) : w;
    const float gate = (w < NW - 1) ? 1.0f : 0.0f;

    if constexpr (I == 9)
        __syncthreads();   // L9 overwrites L5-L8 regions: wait for their readers

    // publish head regs [0,Q) (all lanes, bank-conflict-free)
    #pragma unroll
    for (int j = 0; j < Q; j++) {
        sm->xchB[w][OH + j * 32 + l] = h[j];
        sm->xchB[w][OX + j * 32 + l] = x[j];
    }
    __syncthreads();

    const float* nb = &sm->xchB[wn][0];
    #pragma unroll
    for (int r = 0; r < RR; r++) {
        float hd, xd;
        if (r + Q < RR) {
            hd = h[r + Q];
            xd = x[r + Q];
        } else {
            const int j = r + Q - RR;          // < Q
            hd = gate * nb[OH + j * 32 + l];   // JIT LDS (no prefetch array)
            xd = gate * nb[OX + j * 32 + l];
        }
        float hn = fmaf(wh1, hd, wh0 * h[r]);
        float xn = fmaf(wx1, xd, wx0 * x[r]);
        h[r] = hn;
        x[r] = fast_tanh(hn + xn);
    }
    // no trailing barrier: next layer publishes to a disjoint region (L6-L8)
    // or carries its own pre-publish barrier (L9).
}

// Warp-local contiguous(l*16+r) -> strided(r*32+l) transpose.
// Padded stride 17: writes 17l+r and reads (2r + l/16)*17 + (l&15) are both
// bank-conflict-free. Needs 542 floats of buffer.
__device__ __forceinline__ void transpose16(float (&v)[RR], float* tb, int l) {
    #pragma unroll
    for (int r = 0; r < RR; r++) tb[l * 17 + r] = v[r];
    __syncwarp();
    float t[RR];
    #pragma unroll
    for (int r = 0; r < RR; r++)
        t[r] = tb[(2 * r + (l >> 4)) * 17 + (l & 15)];
    __syncwarp();
    #pragma unroll
    for (int r = 0; r < RR; r++) v[r] = t[r];
}

__global__ __launch_bounds__(THREADS, 2)
void rawstack_kernel(const float* __restrict__ hg,
                     const float* __restrict__ xg,
                     const float* __restrict__ wh,
                     const float* __restrict__ wx,
                     float* __restrict__ out)
{
    extern __shared__ Smem smem_raw[];
    Smem* sm = smem_raw;

    const int tid = threadIdx.x;
    const int w   = tid >> 5;
    const int l   = tid & 31;
    const int tile = blockIdx.x;
    const int b    = blockIdx.y;

    // ---- load 16 consecutive elements per lane into registers ----
    const int in0 = tile * TILE_OUT + w * WCH + l * RR;
    const float* hp = hg + (size_t)b * T_IN + in0;
    const float* xp = xg + (size_t)b * T_IN + in0;

    float h[RR], x[RR];
    if (in0 + RR <= T_IN) {
        #pragma unroll
        for (int r = 0; r < RR; r += 4) {
            float4 a = *reinterpret_cast<const float4*>(hp + r);
            float4 c = *reinterpret_cast<const float4*>(xp + r);
            h[r] = a.x; h[r+1] = a.y; h[r+2] = a.z; h[r+3] = a.w;
            x[r] = c.x; x[r+1] = c.y; x[r+2] = c.z; x[r+3] = c.w;
        }
    } else {
        #pragma unroll
        for (int r = 0; r < RR; r++) {
            const bool ok = (in0 + r < T_IN);
            h[r] = ok ? hp[r] : 0.0f;
            x[r] = ok ? xp[r] : 0.0f;
        }
    }

    // ---- layers 0-4 (contiguous) ----
    layerA<0>(h, x, sm, w, l, wh, wx);
    layerA<1>(h, x, sm, w, l, wh, wx);
    layerA<2>(h, x, sm, w, l, wh, wx);
    layerA<3>(h, x, sm, w, l, wh, wx);
    layerA<4>(h, x, sm, w, l, wh, wx);

    // ---- transpose to strided layout (per-warp region of xchB) ----
    // Warp-local scribble of xchB[w][0..542); cross-warp reads only touch
    // published offsets of the current layer, after that layer's barrier.
    float* tb = &sm->xchB[w][0];
    transpose16(h, tb, l);
    transpose16(x, tb, l);

    // ---- layers 5-9 (strided) ----
    layerB<5>(h, x, sm, w, l, wh, wx);
    layerB<6>(h, x, sm, w, l, wh, wx);
    layerB<7>(h, x, sm, w, l, wh, wx);
    layerB<8>(h, x, sm, w, l, wh, wx);
    layerB<9>(h, x, sm, w, l, wh, wx);

    // ---- store (strided layout -> coalesced STG per r) ----
    if (w < NW - 2) {
        const int obase = tile * TILE_OUT + w * WCH;
        float* op = out + (size_t)b * T_OUT;
        #pragma unroll
        for (int r = 0; r < RR; r++) {
            const int g = obase + r * 32 + l;
            if (g < T_OUT) op[g] = x[r];
        }
    }
}

extern "C" void kernel_launch(void* const* d_in, const int* in_sizes, int n_in,
                              void* d_out, int out_size)
{
    const float* h  = (const float*)d_in[0];
    const float* x  = (const float*)d_in[1];
    const float* wh = (const float*)d_in[2];
    const float* wx = (const float*)d_in[3];
    float* out = (float*)d_out;

    const size_t smem_bytes = sizeof(Smem);   // ~68 KB
    cudaFuncSetAttribute(rawstack_kernel,
                         cudaFuncAttributeMaxDynamicSharedMemorySize,
                         (int)smem_bytes);

    dim3 grid(NTILES, BATCH);
    rawstack_kernel<<<grid, THREADS, smem_bytes>>>(h, x, wh, wx, out);
    (void)in_sizes; (void)n_in; (void)out_size;
}

// round 17
// speedup vs baseline: 1.0584x; 1.0584x over previous
#include <cuda_runtime.h>

// RawStack fused 10-layer dilated conv stack — op-count-reduced version (R13).
// Structure as R12 (RR=16, NW=16, 2 CTAs/SM). Changes:
//  (1) tanh arg via FFMA chain: arg = fma(wx1,xd, fma(wx0,x, hn)) — drops FADD.
//  (2) All phase-B SMEM traffic is float2 {h,x}: STS.64/LDS.64 publishes+reads,
//      and a combined float2 XOR-swizzled transpose (no temp array).

#define T_IN     131072
#define HALO     1023
#define T_OUT    (T_IN - HALO)          // 130049
#define NW       16                     // warps per CTA
#define RR       16                     // elements per lane per array
#define WCH      (RR * 32)              // 512 elements per warp
#define CTA_IN   (NW * WCH)             // 8192
#define TILE_OUT ((NW - 2) * WCH)       // 7168 (warps 14,15 = halo)
#define NTILES   ((T_OUT + TILE_OUT - 1) / TILE_OUT)   // 19
#define THREADS  (NW * 32)              // 512
#define BATCH    64

struct Smem {
    float  xchA[2][NW][32];  // phase-A head exchange: h at [0,16), x at [16,32)
    float2 xchB[NW][512];    // phase-B {h,x} pair exchange; layers 5-8 use
                             // disjoint float2 sub-regions, layer 9 all 512;
                             // also the per-warp float2 transpose buffer
};

// Hardware tanh approximation (MUFU.TANH), single MUFU op.
__device__ __forceinline__ float fast_tanh(float v) {
    float r;
    asm("tanh.approx.f32 %0, %1;" : "=f"(r) : "f"(v));
    return r;
}

// Core update: hn = wh0*h + wh1*hd ; x = tanh(hn + wx0*x + wx1*xd)
__device__ __forceinline__ void upd(float& hr, float& xr, float hd, float xd,
                                    float wh0, float wh1, float wx0, float wx1) {
    float hn  = fmaf(wh1, hd, wh0 * hr);
    float arg = fmaf(wx1, xd, fmaf(wx0, xr, hn));
    hr = hn;
    xr = fast_tanh(arg);
}

// ---- Phase A layer (contiguous layout, elem = l*RR + r): d = 1<<I ----
template<int I>
__device__ __forceinline__ void layerA(float (&h)[RR], float (&x)[RR],
                                       Smem* sm, int w, int l,
                                       const float* __restrict__ wh,
                                       const float* __restrict__ wx)
{
    constexpr int D = 1 << I;      // 1..16
    constexpr int P = I & 1;
    const float wh0 = __ldg(&wh[2*I]), wh1 = __ldg(&wh[2*I+1]);
    const float wx0 = __ldg(&wx[2*I]), wx1 = __ldg(&wx[2*I+1]);

    const int wn = (w < NW - 1) ? (w + 1) : w;     // clamped (no OOB smem)
    const float gate = (w < NW - 1) ? 1.0f : 0.0f; // zero past CTA window

    // publish this warp's lane-0 head [0,D) (pre-update) for warp w-1
    if (l == 0) {
        #pragma unroll
        for (int j = 0; j < D; j++) {
            sm->xchA[P][w][j]      = h[j];
            sm->xchA[P][w][16 + j] = x[j];
        }
    }
    __syncthreads();

    if constexpr (D < RR) {
        // prefetch the D tail-neighbor values (pre-update) before any update
        float nh[D], nx[D];
        #pragma unroll
        for (int j = 0; j < D; j++) {
            float vh = __shfl_down_sync(0xffffffffu, h[j], 1);
            float vx = __shfl_down_sync(0xffffffffu, x[j], 1);
            if (l == 31) {
                vh = gate * sm->xchA[P][wn][j];
                vx = gate * sm->xchA[P][wn][16 + j];
            }
            nh[j] = vh; nx[j] = vx;
        }
        #pragma unroll
        for (int r = 0; r < RR; r++) {
            float hd = (r + D < RR) ? h[r + D] : nh[r + D - RR];
            float xd = (r + D < RR) ? x[r + D] : nx[r + D - RR];
            upd(h[r], x[r], hd, xd, wh0, wh1, wx0, wx1);
        }
    } else {
        // D == RR: every tail value is next lane's h[r]/x[r] -> JIT shfl.
        // Lockstep SIMT + WAR ordering: shfl of h[r] precedes write of h[r].
        #pragma unroll
        for (int r = 0; r < RR; r++) {
            float vh = __shfl_down_sync(0xffffffffu, h[r], 1);
            float vx = __shfl_down_sync(0xffffffffu, x[r], 1);
            if (l == 31) {
                vh = gate * sm->xchA[P][wn][r];
                vx = gate * sm->xchA[P][wn][16 + r];
            }
            upd(h[r], x[r], vh, vx, wh0, wh1, wx0, wx1);
        }
    }
}

// Disjoint xchB float2 sub-region offsets (float2 units, per warp):
//   L5: 0   (Q=1  -> 32)      L6: 32  (Q=2  -> 64)
//   L7: 96  (Q=4  -> 128)     L8: 224 (Q=8  -> 256)   ends at 480 <= 512
//   L9: 0   (Q=16 -> 512)     full buffer, overlaps 5-8 -> pre-barrier
template<int I> struct BOff;
template<> struct BOff<5> { static constexpr int O = 0;   };
template<> struct BOff<6> { static constexpr int O = 32;  };
template<> struct BOff<7> { static constexpr int O = 96;  };
template<> struct BOff<8> { static constexpr int O = 224; };
template<> struct BOff<9> { static constexpr int O = 0;   };

// ---- Phase B layer (strided layout, elem = r*32 + l): d = 32<<(I-5) ----
template<int I>
__device__ __forceinline__ void layerB(float (&h)[RR], float (&x)[RR],
                                       Smem* sm, int w, int l,
                                       const float* __restrict__ wh,
                                       const float* __restrict__ wx)
{
    constexpr int Q = 1 << (I - 5);    // d/32 = 1..16
    constexpr int O = BOff<I>::O;
    const float wh0 = __ldg(&wh[2*I]), wh1 = __ldg(&wh[2*I+1]);
    const float wx0 = __ldg(&wx[2*I]), wx1 = __ldg(&wx[2*I+1]);

    const int wn = (w < NW - 1) ? (w + 1) : w;
    const float gate = (w < NW - 1) ? 1.0f : 0.0f;

    if constexpr (I == 9)
        __syncthreads();   // L9 overwrites L5-L8 regions: wait for their readers

    // publish head regs [0,Q) as {h,x} pairs (STS.64, conflict-free)
    #pragma unroll
    for (int j = 0; j < Q; j++)
        sm->xchB[w][O + j * 32 + l] = make_float2(h[j], x[j]);
    __syncthreads();

    const float2* nb = &sm->xchB[wn][0];
    #pragma unroll
    for (int r = 0; r < RR; r++) {
        float hd, xd;
        if (r + Q < RR) {
            hd = h[r + Q];
            xd = x[r + Q];
        } else {
            const int j = r + Q - RR;          // < Q
            float2 p = nb[O + j * 32 + l];     // JIT LDS.64
            hd = gate * p.x;
            xd = gate * p.y;
        }
        upd(h[r], x[r], hd, xd, wh0, wh1, wx0, wx1);
    }
    // no trailing barrier: next layer publishes to a disjoint region (L6-L8)
    // or carries its own pre-publish barrier (L9).
}

// Combined warp-local {h,x} transpose: contiguous(l*16+r) -> strided(r*32+l).
// float2 buffer, XOR swizzle (r ^ (l&15)) -> conflict-free 64-bit accesses
// both directions. Reads go straight into h/x (no temp array).
__device__ __forceinline__ void transpose16_2(float (&h)[RR], float (&x)[RR],
                                              float2* tb, int l) {
    #pragma unroll
    for (int r = 0; r < RR; r++)
        tb[l * 16 + (r ^ (l & 15))] = make_float2(h[r], x[r]);
    __syncwarp();
    #pragma unroll
    for (int r = 0; r < RR; r++) {
        const int lw = 2 * r + (l >> 4);            // source lane
        float2 v = tb[lw * 16 + ((l & 15) ^ (lw & 15))];
        h[r] = v.x;
        x[r] = v.y;
    }
    __syncwarp();   // protect tb (xchB[w]) reuse by subsequent publishes
}

__global__ __launch_bounds__(THREADS, 2)
void rawstack_kernel(const float* __restrict__ hg,
                     const float* __restrict__ xg,
                     const float* __restrict__ wh,
                     const float* __restrict__ wx,
                     float* __restrict__ out)
{
    extern __shared__ Smem smem_raw[];
    Smem* sm = smem_raw;

    const int tid = threadIdx.x;
    const int w   = tid >> 5;
    const int l   = tid & 31;
    const int tile = blockIdx.x;
    const int b    = blockIdx.y;

    // ---- load 16 consecutive elements per lane into registers ----
    const int in0 = tile * TILE_OUT + w * WCH + l * RR;
    const float* hp = hg + (size_t)b * T_IN + in0;
    const float* xp = xg + (size_t)b * T_IN + in0;

    float h[RR], x[RR];
    if (in0 + RR <= T_IN) {
        #pragma unroll
        for (int r = 0; r < RR; r += 4) {
            float4 a = *reinterpret_cast<const float4*>(hp + r);
            float4 c = *reinterpret_cast<const float4*>(xp + r);
            h[r] = a.x; h[r+1] = a.y; h[r+2] = a.z; h[r+3] = a.w;
            x[r] = c.x; x[r+1] = c.y; x[r+2] = c.z; x[r+3] = c.w;
        }
    } else {
        #pragma unroll
        for (int r = 0; r < RR; r++) {
            const bool ok = (in0 + r < T_IN);
            h[r] = ok ? hp[r] : 0.0f;
            x[r] = ok ? xp[r] : 0.0f;
        }
    }

    // ---- layers 0-4 (contiguous) ----
    layerA<0>(h, x, sm, w, l, wh, wx);
    layerA<1>(h, x, sm, w, l, wh, wx);
    layerA<2>(h, x, sm, w, l, wh, wx);
    layerA<3>(h, x, sm, w, l, wh, wx);
    layerA<4>(h, x, sm, w, l, wh, wx);

    // ---- transpose to strided layout (per-warp region of xchB) ----
    transpose16_2(h, x, &sm->xchB[w][0], l);

    // ---- layers 5-9 (strided) ----
    layerB<5>(h, x, sm, w, l, wh, wx);
    layerB<6>(h, x, sm, w, l, wh, wx);
    layerB<7>(h, x, sm, w, l, wh, wx);
    layerB<8>(h, x, sm, w, l, wh, wx);
    layerB<9>(h, x, sm, w, l, wh, wx);

    // ---- store (strided layout -> coalesced STG per r) ----
    if (w < NW - 2) {
        const int obase = tile * TILE_OUT + w * WCH;
        float* op = out + (size_t)b * T_OUT;
        #pragma unroll
        for (int r = 0; r < RR; r++) {
            const int g = obase + r * 32 + l;
            if (g < T_OUT) op[g] = x[r];
        }
    }
}

extern "C" void kernel_launch(void* const* d_in, const int* in_sizes, int n_in,
                              void* d_out, int out_size)
{
    const float* h  = (const float*)d_in[0];
    const float* x  = (const float*)d_in[1];
    const float* wh = (const float*)d_in[2];
    const float* wx = (const float*)d_in[3];
    float* out = (float*)d_out;

    const size_t smem_bytes = sizeof(Smem);   // ~68 KB
    cudaFuncSetAttribute(rawstack_kernel,
                         cudaFuncAttributeMaxDynamicSharedMemorySize,
                         (int)smem_bytes);

    dim3 grid(NTILES, BATCH);
    rawstack_kernel<<<grid, THREADS, smem_bytes>>>(h, x, wh, wx, out);
    (void)in_sizes; (void)n_in; (void)out_size;
}